// round 2
// baseline (speedup 1.0000x reference)
#include <cuda_runtime.h>
#include <math.h>

// ---------------- problem constants ----------------
#define NB    8
#define CIN   64
#define OO    128
#define HH    64
#define WWID  64
#define KKK   9
#define KDIM  576          // CIN * 9
#define NOFF  1152         // 2 * CIN * 9
#define NMASK 576          // CIN * 9
#define MTOT  32768        // NB * H * W
#define MAXOFF 16.0f

// ---------------- scratch (device globals, allocation-free) ----------------
__device__ float g_col [(size_t)KDIM  * MTOT];   // im2col [k][m]      ~75.5 MB
__device__ float g_off [(size_t)NOFF  * MTOT];   // offsets [n][m]     ~151 MB
__device__ float g_mask[(size_t)NMASK * MTOT];   // mask   [n][m]      ~75.5 MB
__device__ float g_wt  [KDIM * OO];              // w_conv transposed [k][o]

// ---------------- kernel 1: im2col ----------------
__global__ __launch_bounds__(256) void im2col_k(const float* __restrict__ x) {
    int idx = blockIdx.x * 256 + threadIdx.x;          // KDIM*MTOT = 18,874,368
    if (idx >= KDIM * MTOT) return;
    int m = idx & (MTOT - 1);
    int k = idx >> 15;
    int w = m & 63, h = (m >> 6) & 63, b = m >> 12;
    int kk = k % KKK, c = k / KKK;
    int ki = kk / 3, kj = kk % 3;
    int ih = h + ki - 1, iw = w + kj - 1;
    float v = 0.f;
    if ((unsigned)ih < 64u && (unsigned)iw < 64u)
        v = x[(((b * CIN + c) << 6) + ih) * 64 + iw];
    g_col[idx] = v;
}

// ---------------- kernel 1b: transpose w_conv -> [k][o] ----------------
__global__ __launch_bounds__(256) void wt_k(const float* __restrict__ w_conv) {
    int idx = blockIdx.x * 256 + threadIdx.x;          // 576*128 = 73728
    if (idx >= KDIM * OO) return;
    int o = idx & (OO - 1), k = idx >> 7;
    g_wt[idx] = w_conv[o * KDIM + k];
}

// ---------------- kernel 2: fused offset+mask conv as GEMM ----------------
// C[n][m] = sum_k A[n][k] * col[k][m] + bias[n]; n<1152 -> clip +-16 -> g_off
// BM=128 (pixels), BN=64 (channels), BK=16; 256 threads, 8x4 per thread.
#define BM 128
#define BN 64
#define BK 16
__global__ __launch_bounds__(256) void conv_gemm_k(
    const float* __restrict__ w_off, const float* __restrict__ b_off,
    const float* __restrict__ w_mod, const float* __restrict__ b_mod) {

    __shared__ float As[BK][BN + 4];
    __shared__ float Bs[BK][BM];

    const int m0 = blockIdx.x * BM;
    const int n0 = blockIdx.y * BN;

    const float* A;
    const float* bias;
    float* outp;
    bool isOff;
    if (n0 < NOFF) {
        A = w_off + (size_t)n0 * KDIM;
        bias = b_off + n0;
        outp = g_off + (size_t)n0 * MTOT;
        isOff = true;
    } else {
        A = w_mod + (size_t)(n0 - NOFF) * KDIM;
        bias = b_mod + (n0 - NOFF);
        outp = g_mask + (size_t)(n0 - NOFF) * MTOT;
        isOff = false;
    }

    const int tid = threadIdx.x;
    const int tm = tid & 15;   // 16 groups * 8 m  = 128
    const int tn = tid >> 4;   // 16 groups * 4 n  = 64

    const int an  = tid >> 2;         // 0..63
    const int akq = (tid & 3) << 2;   // 0,4,8,12

    float acc[4][8];
#pragma unroll
    for (int i = 0; i < 4; i++)
#pragma unroll
        for (int j = 0; j < 8; j++) acc[i][j] = 0.f;

    for (int k0 = 0; k0 < KDIM; k0 += BK) {
        // load A tile (64n x 16k)
        float4 av = *(const float4*)(A + (size_t)an * KDIM + k0 + akq);
        As[akq + 0][an] = av.x;
        As[akq + 1][an] = av.y;
        As[akq + 2][an] = av.z;
        As[akq + 3][an] = av.w;
        // load B tile (16k x 128m), two float4 per thread
        {
            int q = tid;
            int kk = q >> 5, mq = (q & 31) << 2;
            *(float4*)&Bs[kk][mq] =
                *(const float4*)(g_col + (size_t)(k0 + kk) * MTOT + m0 + mq);
            q = tid + 256;
            kk = q >> 5; mq = (q & 31) << 2;
            *(float4*)&Bs[kk][mq] =
                *(const float4*)(g_col + (size_t)(k0 + kk) * MTOT + m0 + mq);
        }
        __syncthreads();
#pragma unroll
        for (int kk = 0; kk < BK; kk++) {
            float4 a4 = *(const float4*)&As[kk][tn << 2];
            float4 b0 = *(const float4*)&Bs[kk][tm << 3];
            float4 b1 = *(const float4*)&Bs[kk][(tm << 3) + 4];
            float av_[4] = {a4.x, a4.y, a4.z, a4.w};
            float bv_[8] = {b0.x, b0.y, b0.z, b0.w, b1.x, b1.y, b1.z, b1.w};
#pragma unroll
            for (int i = 0; i < 4; i++)
#pragma unroll
                for (int j = 0; j < 8; j++)
                    acc[i][j] = fmaf(av_[i], bv_[j], acc[i][j]);
        }
        __syncthreads();
    }

    // epilogue
#pragma unroll
    for (int i = 0; i < 4; i++) {
        int nl = (tn << 2) + i;
        float bi = bias[nl];
        float* row = outp + (size_t)nl * MTOT + m0 + (tm << 3);
        float v[8];
#pragma unroll
        for (int j = 0; j < 8; j++) {
            float y = acc[i][j] + bi;
            if (isOff) y = fminf(MAXOFF, fmaxf(-MAXOFF, y));
            v[j] = y;
        }
        *(float4*)(row)     = make_float4(v[0], v[1], v[2], v[3]);
        *(float4*)(row + 4) = make_float4(v[4], v[5], v[6], v[7]);
    }
}

// ---------------- kernel 3: deformable sampling + output GEMM ----------------
// One block per (b,h): 64 pixels x 128 outputs. Loop c in chunks of CC=4.
#define CC 4
#define JROWS (CC * KKK)   // 36
__global__ __launch_bounds__(256) void deform_k(const float* __restrict__ x,
                                                float* __restrict__ out) {
    __shared__ float Ss[JROWS][64];      // samples  (9 KB)
    __shared__ float Ws[JROWS][OO];      // weights  (18 KB)

    const int bh = blockIdx.x;           // 0..511
    const int b = bh >> 6, h = bh & 63;
    const int mbase = bh << 6;           // b*4096 + h*64

    const int tid = threadIdx.x;
    const int tw = tid & 15;   // *4 pixels
    const int to = tid >> 4;   // *8 outputs

    float acc[8][4];
#pragma unroll
    for (int i = 0; i < 8; i++)
#pragma unroll
        for (int j = 0; j < 4; j++) acc[i][j] = 0.f;

    const float* xb = x + ((size_t)b * CIN << 12);

    for (int c0 = 0; c0 < CIN; c0 += CC) {
        // load weight chunk: Ws[j][o] = w_conv^T[(c0*9 + j)][o]
        for (int idx = tid; idx < JROWS * OO; idx += 256) {
            int j = idx >> 7, o = idx & (OO - 1);
            Ws[j][o] = g_wt[(c0 * KKK + j) * OO + o];
        }
        // compute samples into Ss
        for (int s = tid; s < JROWS * 64; s += 256) {
            int w = s & 63;
            int j = s >> 6;            // j = cc*9 + kk
            int cc = j / KKK, kk = j - cc * KKK;
            int c = c0 + cc;
            int ki = kk / 3, kj = kk - ki * 3;
            int m = mbase + w;
            int nbase = c * 18 + kk * 2;
            float dy = g_off[(size_t)nbase * MTOT + m];
            float dx = g_off[(size_t)(nbase + 1) * MTOT + m];
            float mv = g_mask[(size_t)(c * KKK + kk) * MTOT + m];

            float py = dy + (float)(h + ki - 1);
            float px = dx + (float)(w + kj - 1);
            float v = 0.f;
            if (py > -1.f && py < 64.f && px > -1.f && px < 64.f) {
                float y0f = floorf(py), x0f = floorf(px);
                float wy = py - y0f, wx = px - x0f;
                int y0 = (int)y0f, x0 = (int)x0f;
                const float* xp = xb + ((size_t)c << 12);
                float v00 = 0.f, v01 = 0.f, v10 = 0.f, v11 = 0.f;
                bool yi0 = (unsigned)y0 < 64u;
                bool yi1 = (unsigned)(y0 + 1) < 64u;
                bool xi0 = (unsigned)x0 < 64u;
                bool xi1 = (unsigned)(x0 + 1) < 64u;
                if (yi0 && xi0) v00 = xp[(y0 << 6) + x0];
                if (yi0 && xi1) v01 = xp[(y0 << 6) + x0 + 1];
                if (yi1 && xi0) v10 = xp[((y0 + 1) << 6) + x0];
                if (yi1 && xi1) v11 = xp[((y0 + 1) << 6) + x0 + 1];
                v = (1.f - wy) * ((1.f - wx) * v00 + wx * v01) +
                    wy * ((1.f - wx) * v10 + wx * v11);
            }
            Ss[j][w] = v * mv;
        }
        __syncthreads();
#pragma unroll 4
        for (int j = 0; j < JROWS; j++) {
            float4 a0 = *(const float4*)&Ws[j][to << 3];
            float4 a1 = *(const float4*)&Ws[j][(to << 3) + 4];
            float4 bv = *(const float4*)&Ss[j][tw << 2];
            float av_[8] = {a0.x, a0.y, a0.z, a0.w, a1.x, a1.y, a1.z, a1.w};
            float bv_[4] = {bv.x, bv.y, bv.z, bv.w};
#pragma unroll
            for (int i = 0; i < 8; i++)
#pragma unroll
                for (int jj = 0; jj < 4; jj++)
                    acc[i][jj] = fmaf(av_[i], bv_[jj], acc[i][jj]);
        }
        __syncthreads();
    }

    // write out[b][o][h][w]
#pragma unroll
    for (int i = 0; i < 8; i++) {
        int o = (to << 3) + i;
        float* op = out + ((((size_t)(b * OO + o)) << 6) + h) * 64 + (tw << 2);
        *(float4*)op = make_float4(acc[i][0], acc[i][1], acc[i][2], acc[i][3]);
    }
}

// ---------------- launch ----------------
extern "C" void kernel_launch(void* const* d_in, const int* in_sizes, int n_in,
                              void* d_out, int out_size) {
    const float* x      = (const float*)d_in[0];
    const float* w_off  = (const float*)d_in[1];
    const float* b_off  = (const float*)d_in[2];
    const float* w_mod  = (const float*)d_in[3];
    const float* b_mod  = (const float*)d_in[4];
    const float* w_conv = (const float*)d_in[5];
    float* out = (float*)d_out;

    im2col_k<<<(KDIM * MTOT + 255) / 256, 256>>>(x);
    wt_k<<<(KDIM * OO + 255) / 256, 256>>>(w_conv);
    conv_gemm_k<<<dim3(MTOT / BM, (NOFF + NMASK) / BN), 256>>>(w_off, b_off, w_mod, b_mod);
    deform_k<<<NB * HH, 256>>>(x, out);
}

// round 6
// speedup vs baseline: 2.0898x; 2.0898x over previous
#include <cuda_runtime.h>
#include <cuda_bf16.h>
#include <cstdint>
#include <math.h>

// ---------------- problem constants ----------------
#define NB    8
#define CIN   64
#define OO    128
#define KKK   9
#define KDIM  576          // CIN * 9
#define NOFF  1152         // 2 * CIN * 9
#define NTOT  1728         // offset + mask channels
#define MTOT  32768        // NB * H * W
#define MAXOFF 16.0f

// ---------------- scratch (device globals, allocation-free) ----------------
__device__ __align__(16) __nv_bfloat16 g_colh[(size_t)MTOT * KDIM];  // im2col hi [m][k]
__device__ __align__(16) __nv_bfloat16 g_coll[(size_t)MTOT * KDIM];  // im2col lo [m][k]
__device__ __align__(16) __nv_bfloat16 g_wh  [(size_t)NTOT * KDIM];  // weights hi [n][k]
__device__ __align__(16) __nv_bfloat16 g_wl  [(size_t)NTOT * KDIM];  // weights lo [n][k]
__device__ float g_bias[NTOT];
__device__ float g_off [(size_t)NOFF * MTOT];            // offsets [n][m]
__device__ float g_mask[(size_t)(NTOT - NOFF) * MTOT];   // mask    [n][m]
__device__ float g_wt  [KDIM * OO];                      // w_conv transposed [k][o]

// ---------------- PTX helpers (baseline sm_80+ features only) ----------------
__device__ __forceinline__ uint32_t smem_u32(const void* p) {
    uint32_t a;
    asm("{ .reg .u64 t; cvta.to.shared.u64 t, %1; cvt.u32.u64 %0, t; }" : "=r"(a) : "l"(p));
    return a;
}
__device__ __forceinline__ void cp_async16(uint32_t dst, const void* src) {
    asm volatile("cp.async.cg.shared.global [%0], [%1], 16;" :: "r"(dst), "l"(src));
}
__device__ __forceinline__ void ldsm_x4(uint32_t& r0, uint32_t& r1, uint32_t& r2, uint32_t& r3,
                                        uint32_t addr) {
    asm volatile("ldmatrix.sync.aligned.m8n8.x4.shared.b16 {%0,%1,%2,%3}, [%4];"
                 : "=r"(r0), "=r"(r1), "=r"(r2), "=r"(r3) : "r"(addr));
}
__device__ __forceinline__ void mma16816(float* d, const uint32_t* a, const uint32_t* b) {
    asm volatile(
        "mma.sync.aligned.m16n8k16.row.col.f32.bf16.bf16.f32 "
        "{%0,%1,%2,%3}, {%4,%5,%6,%7}, {%8,%9}, {%0,%1,%2,%3};"
        : "+f"(d[0]), "+f"(d[1]), "+f"(d[2]), "+f"(d[3])
        : "r"(a[0]), "r"(a[1]), "r"(a[2]), "r"(a[3]), "r"(b[0]), "r"(b[1]));
}

// ---------------- kernel 1: im2col -> bf16 hi/lo in [m][k] layout ----------------
__global__ __launch_bounds__(576) void im2col_bf16_k(const float* __restrict__ x) {
    const int m = blockIdx.x;
    const int k = threadIdx.x;          // 0..575
    const int w = m & 63, h = (m >> 6) & 63, b = m >> 12;
    const int c = k / KKK, kk = k - c * KKK;
    const int ki = kk / 3, kj = kk - ki * 3;
    const int ih = h + ki - 1, iw = w + kj - 1;
    float v = 0.f;
    if ((unsigned)ih < 64u && (unsigned)iw < 64u)
        v = x[(((b * CIN + c) << 6) + ih) * 64 + iw];
    __nv_bfloat16 hi = __float2bfloat16(v);
    __nv_bfloat16 lo = __float2bfloat16(v - __bfloat162float(hi));
    size_t idx = (size_t)m * KDIM + k;
    g_colh[idx] = hi;
    g_coll[idx] = lo;
}

// ---------------- kernel 2: weight split + bias merge ----------------
__global__ __launch_bounds__(576) void wprep_k(const float* __restrict__ w_off,
                                               const float* __restrict__ b_off,
                                               const float* __restrict__ w_mod,
                                               const float* __restrict__ b_mod) {
    const int n = blockIdx.x;           // 0..1727
    const int k = threadIdx.x;          // 0..575
    float v = (n < NOFF) ? w_off[(size_t)n * KDIM + k]
                         : w_mod[(size_t)(n - NOFF) * KDIM + k];
    __nv_bfloat16 hi = __float2bfloat16(v);
    __nv_bfloat16 lo = __float2bfloat16(v - __bfloat162float(hi));
    size_t idx = (size_t)n * KDIM + k;
    g_wh[idx] = hi;
    g_wl[idx] = lo;
    if (k == 0)
        g_bias[n] = (n < NOFF) ? b_off[n] : b_mod[n - NOFF];
}

// ---------------- kernel 2b: transpose w_conv -> [k][o] ----------------
__global__ __launch_bounds__(256) void wt_k(const float* __restrict__ w_conv) {
    int idx = blockIdx.x * 256 + threadIdx.x;
    if (idx >= KDIM * OO) return;
    int o = idx & (OO - 1), k = idx >> 7;
    g_wt[idx] = w_conv[o * KDIM + k];
}

// ---------------- kernel 3: mma.sync bf16x3 GEMM for offset+mask conv ----------------
// D[m][n] = sum_k col[m][k] * w[n][k]. Virtual K = 3*576 (AhBh, AlBh, AhBl).
#define BM 128
#define BN 192
#define BK 32
#define NSTAGE 3
#define A_STAGE (BM * BK * 2)            // 8192 B
#define B_STAGE (BN * BK * 2)            // 12288 B
#define STAGE_B (A_STAGE + B_STAGE)      // 20480 B
#define GEMM_SMEM (NSTAGE * STAGE_B)     // 61440 B
#define KCH 18                           // 576/32
#define VCHUNKS (3 * KCH)                // 54

// XOR swizzle: 16B chunk c of row r -> c ^ ((r>>1)&3)
__device__ __forceinline__ int swz16(int r, int c) { return c ^ ((r >> 1) & 3); }

__global__ void __launch_bounds__(256, 1) gemm_mma_k() {
    extern __shared__ char sm[];
    const int tid = threadIdx.x;
    const int wid = tid >> 5;
    const int lane = tid & 31;
    const int warp_m = wid & 3;      // 4 warps along m
    const int warp_n = wid >> 2;     // 2 warps along n
    const int m0 = blockIdx.x * BM;
    const int n0 = blockIdx.y * BN;
    const uint32_t smem_base = smem_u32(sm);

    float acc[2][12][4];
#pragma unroll
    for (int i = 0; i < 2; i++)
#pragma unroll
        for (int j = 0; j < 12; j++)
#pragma unroll
            for (int q = 0; q < 4; q++) acc[i][j][q] = 0.f;

    // stage loader
    auto load_stage = [&](int s, int chunk) {
        const int seg = chunk / KCH;
        const int k0 = (chunk - seg * KCH) * BK;
        const __nv_bfloat16* Asrc = (seg == 1) ? g_coll : g_colh;
        const __nv_bfloat16* Bsrc = (seg == 2) ? g_wl : g_wh;
        const uint32_t ab = smem_base + s * STAGE_B;
        const uint32_t bb = ab + A_STAGE;
#pragma unroll
        for (int i = 0; i < 2; i++) {          // A: 512 chunks of 16B
            int e = tid + i * 256;
            int r = e >> 2, c = e & 3;
            cp_async16(ab + r * 64 + swz16(r, c) * 16,
                       Asrc + (size_t)(m0 + r) * KDIM + k0 + c * 8);
        }
#pragma unroll
        for (int i = 0; i < 3; i++) {          // B: 768 chunks
            int e = tid + i * 256;
            int r = e >> 2, c = e & 3;
            cp_async16(bb + r * 64 + swz16(r, c) * 16,
                       Bsrc + (size_t)(n0 + r) * KDIM + k0 + c * 8);
        }
    };

    load_stage(0, 0);
    asm volatile("cp.async.commit_group;");
    load_stage(1, 1);
    asm volatile("cp.async.commit_group;");

    for (int q = 0; q < VCHUNKS; q++) {
        if (q + 2 < VCHUNKS) load_stage((q + 2) % NSTAGE, q + 2);
        asm volatile("cp.async.commit_group;");
        asm volatile("cp.async.wait_group 2;");
        __syncthreads();

        const uint32_t ab = smem_base + (q % NSTAGE) * STAGE_B;
        const uint32_t bb = ab + A_STAGE;
#pragma unroll
        for (int ks = 0; ks < 2; ks++) {
            uint32_t a[2][4];
#pragma unroll
            for (int mf = 0; mf < 2; mf++) {
                int r = warp_m * 32 + mf * 16 + (lane & 15);
                int c = ks * 2 + (lane >> 4);
                ldsm_x4(a[mf][0], a[mf][1], a[mf][2], a[mf][3],
                        ab + r * 64 + swz16(r, c) * 16);
            }
#pragma unroll
            for (int nfp = 0; nfp < 6; nfp++) {
                int r = warp_n * 96 + nfp * 16 + (lane & 7) + ((lane >> 4) & 1) * 8;
                int c = ks * 2 + ((lane >> 3) & 1);
                uint32_t b[4];
                ldsm_x4(b[0], b[1], b[2], b[3], bb + r * 64 + swz16(r, c) * 16);
                mma16816(acc[0][2 * nfp],     a[0], b);
                mma16816(acc[0][2 * nfp + 1], a[0], b + 2);
                mma16816(acc[1][2 * nfp],     a[1], b);
                mma16816(acc[1][2 * nfp + 1], a[1], b + 2);
            }
        }
        __syncthreads();
    }

    // ---------------- epilogue: transpose via SMEM, coalesced [n][m] stores ----------------
    float* ws = (float*)sm + wid * (48 * 33);   // 8 warps x 6336B = 50688B <= 61440B
#pragma unroll
    for (int pass = 0; pass < 2; pass++) {
#pragma unroll
        for (int mf = 0; mf < 2; mf++)
#pragma unroll
            for (int nf6 = 0; nf6 < 6; nf6++) {
                int nf = pass * 6 + nf6;
#pragma unroll
                for (int j = 0; j < 4; j++) {
                    int nl = nf6 * 8 + (lane & 3) * 2 + (j & 1);
                    int ml = mf * 16 + ((j >> 1) & 1) * 8 + (lane >> 2);
                    ws[nl * 33 + ml] = acc[mf][nf][j];
                }
            }
        __syncwarp();
        const int m = m0 + warp_m * 32 + lane;
#pragma unroll 4
        for (int row = 0; row < 48; row++) {
            int n = n0 + warp_n * 96 + pass * 48 + row;
            float v = ws[row * 33 + lane] + g_bias[n];
            if (n < NOFF) {
                v = fminf(MAXOFF, fmaxf(-MAXOFF, v));
                g_off[(size_t)n * MTOT + m] = v;
            } else {
                g_mask[(size_t)(n - NOFF) * MTOT + m] = v;
            }
        }
        __syncwarp();
    }
}

// ---------------- kernel 4: deformable sampling + output GEMM ----------------
#define CC 4
#define JROWS (CC * KKK)   // 36
__global__ __launch_bounds__(256) void deform_k(const float* __restrict__ x,
                                                float* __restrict__ out) {
    __shared__ float Ss[JROWS][64];
    __shared__ float Ws[JROWS][OO];

    const int bh = blockIdx.x;
    const int b = bh >> 6, h = bh & 63;
    const int mbase = bh << 6;

    const int tid = threadIdx.x;
    const int tw = tid & 15;
    const int to = tid >> 4;

    float acc[8][4];
#pragma unroll
    for (int i = 0; i < 8; i++)
#pragma unroll
        for (int j = 0; j < 4; j++) acc[i][j] = 0.f;

    const float* xb = x + ((size_t)b * CIN << 12);

    for (int c0 = 0; c0 < CIN; c0 += CC) {
        for (int idx = tid; idx < JROWS * OO; idx += 256) {
            int j = idx >> 7, o = idx & (OO - 1);
            Ws[j][o] = g_wt[(c0 * KKK + j) * OO + o];
        }
        for (int s = tid; s < JROWS * 64; s += 256) {
            int w = s & 63;
            int j = s >> 6;
            int cc = j / KKK, kk = j - cc * KKK;
            int c = c0 + cc;
            int ki = kk / 3, kj = kk - ki * 3;
            int m = mbase + w;
            int nbase = c * 18 + kk * 2;
            float dy = g_off[(size_t)nbase * MTOT + m];
            float dx = g_off[(size_t)(nbase + 1) * MTOT + m];
            float mv = g_mask[(size_t)(c * KKK + kk) * MTOT + m];

            float py = dy + (float)(h + ki - 1);
            float px = dx + (float)(w + kj - 1);
            float v = 0.f;
            if (py > -1.f && py < 64.f && px > -1.f && px < 64.f) {
                float y0f = floorf(py), x0f = floorf(px);
                float wy = py - y0f, wx = px - x0f;
                int y0 = (int)y0f, x0 = (int)x0f;
                const float* xp = xb + ((size_t)c << 12);
                float v00 = 0.f, v01 = 0.f, v10 = 0.f, v11 = 0.f;
                bool yi0 = (unsigned)y0 < 64u;
                bool yi1 = (unsigned)(y0 + 1) < 64u;
                bool xi0 = (unsigned)x0 < 64u;
                bool xi1 = (unsigned)(x0 + 1) < 64u;
                if (yi0 && xi0) v00 = xp[(y0 << 6) + x0];
                if (yi0 && xi1) v01 = xp[(y0 << 6) + x0 + 1];
                if (yi1 && xi0) v10 = xp[((y0 + 1) << 6) + x0];
                if (yi1 && xi1) v11 = xp[((y0 + 1) << 6) + x0 + 1];
                v = (1.f - wy) * ((1.f - wx) * v00 + wx * v01) +
                    wy * ((1.f - wx) * v10 + wx * v11);
            }
            Ss[j][w] = v * mv;
        }
        __syncthreads();
#pragma unroll 4
        for (int j = 0; j < JROWS; j++) {
            float4 a0 = *(const float4*)&Ws[j][to << 3];
            float4 a1 = *(const float4*)&Ws[j][(to << 3) + 4];
            float4 bv = *(const float4*)&Ss[j][tw << 2];
            float av_[8] = {a0.x, a0.y, a0.z, a0.w, a1.x, a1.y, a1.z, a1.w};
            float bv_[4] = {bv.x, bv.y, bv.z, bv.w};
#pragma unroll
            for (int i = 0; i < 8; i++)
#pragma unroll
                for (int jj = 0; jj < 4; jj++)
                    acc[i][jj] = fmaf(av_[i], bv_[jj], acc[i][jj]);
        }
        __syncthreads();
    }

#pragma unroll
    for (int i = 0; i < 8; i++) {
        int o = (to << 3) + i;
        float* op = out + ((((size_t)(b * OO + o)) << 6) + h) * 64 + (tw << 2);
        *(float4*)op = make_float4(acc[i][0], acc[i][1], acc[i][2], acc[i][3]);
    }
}

// ---------------- launch ----------------
extern "C" void kernel_launch(void* const* d_in, const int* in_sizes, int n_in,
                              void* d_out, int out_size) {
    const float* x      = (const float*)d_in[0];
    const float* w_off  = (const float*)d_in[1];
    const float* b_off  = (const float*)d_in[2];
    const float* w_mod  = (const float*)d_in[3];
    const float* b_mod  = (const float*)d_in[4];
    const float* w_conv = (const float*)d_in[5];
    float* out = (float*)d_out;

    static int smem_set = 0;
    if (!smem_set) {
        cudaFuncSetAttribute(gemm_mma_k, cudaFuncAttributeMaxDynamicSharedMemorySize, GEMM_SMEM);
        smem_set = 1;
    }

    im2col_bf16_k<<<MTOT, 576>>>(x);
    wprep_k<<<NTOT, 576>>>(w_off, b_off, w_mod, b_mod);
    wt_k<<<(KDIM * OO + 255) / 256, 256>>>(w_conv);
    gemm_mma_k<<<dim3(MTOT / BM, NTOT / BN), 256, GEMM_SMEM>>>();
    deform_k<<<NB * 64, 256>>>(x, out);
}

// round 7
// speedup vs baseline: 2.5669x; 1.2283x over previous
#include <cuda_runtime.h>
#include <cuda_bf16.h>
#include <cstdint>
#include <math.h>

// ---------------- problem constants ----------------
#define NB    8
#define CIN   64
#define OO    128
#define KKK   9
#define KDIM  576          // CIN * 9
#define NOFF  1152         // 2 * CIN * 9
#define NTOT  1728         // offset + mask channels
#define MTOT  32768        // NB * H * W
#define MAXOFF 16.0f

// ---------------- scratch (device globals, allocation-free) ----------------
__device__ __align__(16) __nv_bfloat16 g_colh[(size_t)MTOT * KDIM];  // im2col hi [m][k]
__device__ __align__(16) __nv_bfloat16 g_coll[(size_t)MTOT * KDIM];  // im2col lo [m][k]
__device__ __align__(16) __nv_bfloat16 g_wh  [(size_t)NTOT * KDIM];  // weights hi [n][k]
__device__ __align__(16) __nv_bfloat16 g_wl  [(size_t)NTOT * KDIM];  // weights lo [n][k]
__device__ float g_bias[NTOT];
__device__ float g_off [(size_t)NOFF * MTOT];            // offsets [n][m]
__device__ float g_mask[(size_t)(NTOT - NOFF) * MTOT];   // mask    [n][m]
__device__ float g_wt  [KDIM * OO];                      // w_conv transposed [k][o]

// ---------------- PTX helpers (baseline sm_80+ features only) ----------------
__device__ __forceinline__ uint32_t smem_u32(const void* p) {
    uint32_t a;
    asm("{ .reg .u64 t; cvta.to.shared.u64 t, %1; cvt.u32.u64 %0, t; }" : "=r"(a) : "l"(p));
    return a;
}
__device__ __forceinline__ void cp_async16(uint32_t dst, const void* src) {
    asm volatile("cp.async.cg.shared.global [%0], [%1], 16;" :: "r"(dst), "l"(src));
}
__device__ __forceinline__ void ldsm_x4(uint32_t& r0, uint32_t& r1, uint32_t& r2, uint32_t& r3,
                                        uint32_t addr) {
    asm volatile("ldmatrix.sync.aligned.m8n8.x4.shared.b16 {%0,%1,%2,%3}, [%4];"
                 : "=r"(r0), "=r"(r1), "=r"(r2), "=r"(r3) : "r"(addr));
}
__device__ __forceinline__ void mma16816(float* d, const uint32_t* a, const uint32_t* b) {
    asm volatile(
        "mma.sync.aligned.m16n8k16.row.col.f32.bf16.bf16.f32 "
        "{%0,%1,%2,%3}, {%4,%5,%6,%7}, {%8,%9}, {%0,%1,%2,%3};"
        : "+f"(d[0]), "+f"(d[1]), "+f"(d[2]), "+f"(d[3])
        : "r"(a[0]), "r"(a[1]), "r"(a[2]), "r"(a[3]), "r"(b[0]), "r"(b[1]));
}

// ---------------- kernel 1: im2col -> bf16 hi/lo in [m][k] layout ----------------
__global__ __launch_bounds__(576) void im2col_bf16_k(const float* __restrict__ x) {
    const int m = blockIdx.x;
    const int k = threadIdx.x;          // 0..575
    const int w = m & 63, h = (m >> 6) & 63, b = m >> 12;
    const int c = k / KKK, kk = k - c * KKK;
    const int ki = kk / 3, kj = kk - ki * 3;
    const int ih = h + ki - 1, iw = w + kj - 1;
    float v = 0.f;
    if ((unsigned)ih < 64u && (unsigned)iw < 64u)
        v = x[(((b * CIN + c) << 6) + ih) * 64 + iw];
    __nv_bfloat16 hi = __float2bfloat16(v);
    __nv_bfloat16 lo = __float2bfloat16(v - __bfloat162float(hi));
    size_t idx = (size_t)m * KDIM + k;
    g_colh[idx] = hi;
    g_coll[idx] = lo;
}

// ---------------- kernel 2: weight split + bias merge ----------------
__global__ __launch_bounds__(576) void wprep_k(const float* __restrict__ w_off,
                                               const float* __restrict__ b_off,
                                               const float* __restrict__ w_mod,
                                               const float* __restrict__ b_mod) {
    const int n = blockIdx.x;           // 0..1727
    const int k = threadIdx.x;          // 0..575
    float v = (n < NOFF) ? w_off[(size_t)n * KDIM + k]
                         : w_mod[(size_t)(n - NOFF) * KDIM + k];
    __nv_bfloat16 hi = __float2bfloat16(v);
    __nv_bfloat16 lo = __float2bfloat16(v - __bfloat162float(hi));
    size_t idx = (size_t)n * KDIM + k;
    g_wh[idx] = hi;
    g_wl[idx] = lo;
    if (k == 0)
        g_bias[n] = (n < NOFF) ? b_off[n] : b_mod[n - NOFF];
}

// ---------------- kernel 2b: transpose w_conv -> [k][o] ----------------
__global__ __launch_bounds__(256) void wt_k(const float* __restrict__ w_conv) {
    int idx = blockIdx.x * 256 + threadIdx.x;
    if (idx >= KDIM * OO) return;
    int o = idx & (OO - 1), k = idx >> 7;
    g_wt[idx] = w_conv[o * KDIM + k];
}

// ---------------- kernel 3: mma.sync bf16x3 GEMM for offset+mask conv ----------------
// D[m][n] = sum_k col[m][k] * w[n][k]. Virtual K = 3*576 (AhBh, AlBh, AhBl).
// BM=128, BN=96, BK=64, 3 stages, 1 sync per chunk, 2 CTAs/SM.
#define BM 128
#define BN 96
#define BK 64
#define NSTAGE 3
#define A_STAGE (BM * BK * 2)            // 16384 B
#define B_STAGE (BN * BK * 2)            // 12288 B
#define STAGE_B (A_STAGE + B_STAGE)      // 28672 B
#define GEMM_SMEM (NSTAGE * STAGE_B)     // 86016 B
#define KCH 9                            // 576/64
#define VCHUNKS (3 * KCH)                // 27

// XOR swizzle: row r (128B), 16B chunk c (0..7) -> c ^ (r & 7)
__device__ __forceinline__ int swz(int r, int c) { return c ^ (r & 7); }

__global__ void __launch_bounds__(256, 2) gemm_mma_k() {
    extern __shared__ char sm[];
    const int tid = threadIdx.x;
    const int wid = tid >> 5;
    const int lane = tid & 31;
    const int warp_m = wid & 3;      // 4 warps along m (32 each)
    const int warp_n = wid >> 2;     // 2 warps along n (48 each)
    const int m0 = blockIdx.x * BM;
    const int n0 = blockIdx.y * BN;
    const uint32_t smem_base = smem_u32(sm);

    float acc[2][6][4];
#pragma unroll
    for (int i = 0; i < 2; i++)
#pragma unroll
        for (int j = 0; j < 6; j++)
#pragma unroll
            for (int q = 0; q < 4; q++) acc[i][j][q] = 0.f;

    auto load_stage = [&](int s, int chunk) {
        const int seg = chunk / KCH;
        const int k0 = (chunk - seg * KCH) * BK;
        const __nv_bfloat16* Asrc = (seg == 1) ? g_coll : g_colh;
        const __nv_bfloat16* Bsrc = (seg == 2) ? g_wl : g_wh;
        const uint32_t ab = smem_base + s * STAGE_B;
        const uint32_t bb = ab + A_STAGE;
#pragma unroll
        for (int i = 0; i < 4; i++) {          // A: 1024 chunks of 16B
            int e = tid + i * 256;
            int r = e >> 3, c = e & 7;
            cp_async16(ab + r * 128 + swz(r, c) * 16,
                       Asrc + (size_t)(m0 + r) * KDIM + k0 + c * 8);
        }
#pragma unroll
        for (int i = 0; i < 3; i++) {          // B: 768 chunks
            int e = tid + i * 256;
            int r = e >> 3, c = e & 7;
            cp_async16(bb + r * 128 + swz(r, c) * 16,
                       Bsrc + (size_t)(n0 + r) * KDIM + k0 + c * 8);
        }
        asm volatile("cp.async.commit_group;");
    };

    load_stage(0, 0);
    load_stage(1, 1);

    for (int q = 0; q < VCHUNKS; q++) {
        asm volatile("cp.async.wait_group 1;");
        __syncthreads();
        // issue next stage AFTER the barrier: barrier proves every warp has
        // finished computing chunk q-1, whose buffer (q+2)%3 we now overwrite.
        if (q + 2 < VCHUNKS) load_stage((q + 2) % NSTAGE, q + 2);

        const uint32_t ab = smem_base + (q % NSTAGE) * STAGE_B;
        const uint32_t bb = ab + A_STAGE;
#pragma unroll
        for (int ks = 0; ks < 4; ks++) {       // 4 x k16 within BK=64
            uint32_t a[2][4];
#pragma unroll
            for (int mf = 0; mf < 2; mf++) {
                int r = warp_m * 32 + mf * 16 + (lane & 15);
                int c = ks * 2 + (lane >> 4);
                ldsm_x4(a[mf][0], a[mf][1], a[mf][2], a[mf][3],
                        ab + r * 128 + swz(r, c) * 16);
            }
#pragma unroll
            for (int nfp = 0; nfp < 3; nfp++) {
                int r = warp_n * 48 + nfp * 16 + (lane & 7) + ((lane >> 4) & 1) * 8;
                int c = ks * 2 + ((lane >> 3) & 1);
                uint32_t b[4];
                ldsm_x4(b[0], b[1], b[2], b[3], bb + r * 128 + swz(r, c) * 16);
                mma16816(acc[0][2 * nfp],     a[0], b);
                mma16816(acc[0][2 * nfp + 1], a[0], b + 2);
                mma16816(acc[1][2 * nfp],     a[1], b);
                mma16816(acc[1][2 * nfp + 1], a[1], b + 2);
            }
        }
    }
    __syncthreads();

    // ---------------- epilogue: transpose via SMEM, coalesced [n][m] stores ----------------
    float* ws = (float*)sm + wid * (48 * 33);   // 8 warps x 6336B = 50688B <= 86016B
#pragma unroll
    for (int mf = 0; mf < 2; mf++)
#pragma unroll
        for (int nf = 0; nf < 6; nf++)
#pragma unroll
            for (int j = 0; j < 4; j++) {
                int nl = (nf >> 1) * 16 + (nf & 1) * 8 + (lane & 3) * 2 + (j & 1);
                int ml = mf * 16 + ((j >> 1) & 1) * 8 + (lane >> 2);
                ws[nl * 33 + ml] = acc[mf][nf][j];
            }
    __syncwarp();
    {
        const int m = m0 + warp_m * 32 + lane;
#pragma unroll 4
        for (int row = 0; row < 48; row++) {
            int n = n0 + warp_n * 48 + row;
            float v = ws[row * 33 + lane] + g_bias[n];
            if (n < NOFF) {
                v = fminf(MAXOFF, fmaxf(-MAXOFF, v));
                g_off[(size_t)n * MTOT + m] = v;
            } else {
                g_mask[(size_t)(n - NOFF) * MTOT + m] = v;
            }
        }
    }
}

// ---------------- kernel 4: deformable sampling + output GEMM ----------------
#define CC 4
#define JROWS (CC * KKK)   // 36
__global__ __launch_bounds__(256) void deform_k(const float* __restrict__ x,
                                                float* __restrict__ out) {
    __shared__ float Ss[JROWS][64];
    __shared__ float Ws[JROWS][OO];

    const int bh = blockIdx.x;
    const int b = bh >> 6, h = bh & 63;
    const int mbase = bh << 6;

    const int tid = threadIdx.x;
    const int tw = tid & 15;
    const int to = tid >> 4;

    float acc[8][4];
#pragma unroll
    for (int i = 0; i < 8; i++)
#pragma unroll
        for (int j = 0; j < 4; j++) acc[i][j] = 0.f;

    const float* xb = x + ((size_t)b * CIN << 12);

    for (int c0 = 0; c0 < CIN; c0 += CC) {
        for (int idx = tid; idx < JROWS * OO; idx += 256) {
            int j = idx >> 7, o = idx & (OO - 1);
            Ws[j][o] = g_wt[(c0 * KKK + j) * OO + o];
        }
        for (int s = tid; s < JROWS * 64; s += 256) {
            int w = s & 63;
            int j = s >> 6;
            int cc = j / KKK, kk = j - cc * KKK;
            int c = c0 + cc;
            int ki = kk / 3, kj = kk - ki * 3;
            int m = mbase + w;
            int nbase = c * 18 + kk * 2;
            float dy = g_off[(size_t)nbase * MTOT + m];
            float dx = g_off[(size_t)(nbase + 1) * MTOT + m];
            float mv = g_mask[(size_t)(c * KKK + kk) * MTOT + m];

            float py = dy + (float)(h + ki - 1);
            float px = dx + (float)(w + kj - 1);
            float v = 0.f;
            if (py > -1.f && py < 64.f && px > -1.f && px < 64.f) {
                float y0f = floorf(py), x0f = floorf(px);
                float wy = py - y0f, wx = px - x0f;
                int y0 = (int)y0f, x0 = (int)x0f;
                const float* xp = xb + ((size_t)c << 12);
                float v00 = 0.f, v01 = 0.f, v10 = 0.f, v11 = 0.f;
                bool yi0 = (unsigned)y0 < 64u;
                bool yi1 = (unsigned)(y0 + 1) < 64u;
                bool xi0 = (unsigned)x0 < 64u;
                bool xi1 = (unsigned)(x0 + 1) < 64u;
                if (yi0 && xi0) v00 = xp[(y0 << 6) + x0];
                if (yi0 && xi1) v01 = xp[(y0 << 6) + x0 + 1];
                if (yi1 && xi0) v10 = xp[((y0 + 1) << 6) + x0];
                if (yi1 && xi1) v11 = xp[((y0 + 1) << 6) + x0 + 1];
                v = (1.f - wy) * ((1.f - wx) * v00 + wx * v01) +
                    wy * ((1.f - wx) * v10 + wx * v11);
            }
            Ss[j][w] = v * mv;
        }
        __syncthreads();
#pragma unroll 4
        for (int j = 0; j < JROWS; j++) {
            float4 a0 = *(const float4*)&Ws[j][to << 3];
            float4 a1 = *(const float4*)&Ws[j][(to << 3) + 4];
            float4 bv = *(const float4*)&Ss[j][tw << 2];
            float av_[8] = {a0.x, a0.y, a0.z, a0.w, a1.x, a1.y, a1.z, a1.w};
            float bv_[4] = {bv.x, bv.y, bv.z, bv.w};
#pragma unroll
            for (int i = 0; i < 8; i++)
#pragma unroll
                for (int jj = 0; jj < 4; jj++)
                    acc[i][jj] = fmaf(av_[i], bv_[jj], acc[i][jj]);
        }
        __syncthreads();
    }

#pragma unroll
    for (int i = 0; i < 8; i++) {
        int o = (to << 3) + i;
        float* op = out + ((((size_t)(b * OO + o)) << 6) + h) * 64 + (tw << 2);
        *(float4*)op = make_float4(acc[i][0], acc[i][1], acc[i][2], acc[i][3]);
    }
}

// ---------------- launch ----------------
extern "C" void kernel_launch(void* const* d_in, const int* in_sizes, int n_in,
                              void* d_out, int out_size) {
    const float* x      = (const float*)d_in[0];
    const float* w_off  = (const float*)d_in[1];
    const float* b_off  = (const float*)d_in[2];
    const float* w_mod  = (const float*)d_in[3];
    const float* b_mod  = (const float*)d_in[4];
    const float* w_conv = (const float*)d_in[5];
    float* out = (float*)d_out;

    static int smem_set = 0;
    if (!smem_set) {
        cudaFuncSetAttribute(gemm_mma_k, cudaFuncAttributeMaxDynamicSharedMemorySize, GEMM_SMEM);
        smem_set = 1;
    }

    im2col_bf16_k<<<MTOT, 576>>>(x);
    wprep_k<<<NTOT, 576>>>(w_off, b_off, w_mod, b_mod);
    wt_k<<<(KDIM * OO + 255) / 256, 256>>>(w_conv);
    gemm_mma_k<<<dim3(MTOT / BM, NTOT / BN), 256, GEMM_SMEM>>>();
    deform_k<<<NB * 64, 256>>>(x, out);
}

// round 8
// speedup vs baseline: 3.2987x; 1.2851x over previous
#include <cuda_runtime.h>
#include <cuda_bf16.h>
#include <cstdint>
#include <math.h>

// ---------------- problem constants ----------------
#define NB    8
#define CIN   64
#define OO    128
#define KKK   9
#define KDIM  576          // CIN * 9
#define NOFF  1152         // 2 * CIN * 9
#define NTOT  1728         // offset + mask channels
#define MTOT  32768        // NB * H * W
#define MAXOFF 16.0f

// ---------------- scratch (device globals, allocation-free) ----------------
// g_colh/g_coll double as: im2col [m][k] for gemm_mma_k, then sample matrix
// [j][m] for out_gemm_k (gemm_mma_k completes before sample_k overwrites).
__device__ __align__(16) __nv_bfloat16 g_colh[(size_t)MTOT * KDIM];
__device__ __align__(16) __nv_bfloat16 g_coll[(size_t)MTOT * KDIM];
__device__ __align__(16) __nv_bfloat16 g_wh  [(size_t)NTOT * KDIM];  // conv weights hi [n][k]
__device__ __align__(16) __nv_bfloat16 g_wl  [(size_t)NTOT * KDIM];  // conv weights lo [n][k]
__device__ __align__(16) __nv_bfloat16 g_wch [OO * KDIM];            // w_conv hi [o][j]
__device__ __align__(16) __nv_bfloat16 g_wcl [OO * KDIM];            // w_conv lo [o][j]
__device__ float g_bias[NTOT];
__device__ float g_off [(size_t)NOFF * MTOT];            // offsets [n][m]
__device__ float g_mask[(size_t)(NTOT - NOFF) * MTOT];   // mask    [n][m]

// ---------------- PTX helpers (baseline sm_80+ features only) ----------------
__device__ __forceinline__ uint32_t smem_u32(const void* p) {
    uint32_t a;
    asm("{ .reg .u64 t; cvta.to.shared.u64 t, %1; cvt.u32.u64 %0, t; }" : "=r"(a) : "l"(p));
    return a;
}
__device__ __forceinline__ void cp_async16(uint32_t dst, const void* src) {
    asm volatile("cp.async.cg.shared.global [%0], [%1], 16;" :: "r"(dst), "l"(src));
}
__device__ __forceinline__ void ldsm_x4(uint32_t& r0, uint32_t& r1, uint32_t& r2, uint32_t& r3,
                                        uint32_t addr) {
    asm volatile("ldmatrix.sync.aligned.m8n8.x4.shared.b16 {%0,%1,%2,%3}, [%4];"
                 : "=r"(r0), "=r"(r1), "=r"(r2), "=r"(r3) : "r"(addr));
}
__device__ __forceinline__ void ldsm_x4t(uint32_t& r0, uint32_t& r1, uint32_t& r2, uint32_t& r3,
                                         uint32_t addr) {
    asm volatile("ldmatrix.sync.aligned.m8n8.x4.trans.shared.b16 {%0,%1,%2,%3}, [%4];"
                 : "=r"(r0), "=r"(r1), "=r"(r2), "=r"(r3) : "r"(addr));
}
__device__ __forceinline__ void mma16816(float* d, const uint32_t* a, const uint32_t* b) {
    asm volatile(
        "mma.sync.aligned.m16n8k16.row.col.f32.bf16.bf16.f32 "
        "{%0,%1,%2,%3}, {%4,%5,%6,%7}, {%8,%9}, {%0,%1,%2,%3};"
        : "+f"(d[0]), "+f"(d[1]), "+f"(d[2]), "+f"(d[3])
        : "r"(a[0]), "r"(a[1]), "r"(a[2]), "r"(a[3]), "r"(b[0]), "r"(b[1]));
}

// ---------------- kernel 1: im2col -> bf16 hi/lo in [m][k] layout ----------------
__global__ __launch_bounds__(576) void im2col_bf16_k(const float* __restrict__ x) {
    const int m = blockIdx.x;
    const int k = threadIdx.x;          // 0..575
    const int w = m & 63, h = (m >> 6) & 63, b = m >> 12;
    const int c = k / KKK, kk = k - c * KKK;
    const int ki = kk / 3, kj = kk - ki * 3;
    const int ih = h + ki - 1, iw = w + kj - 1;
    float v = 0.f;
    if ((unsigned)ih < 64u && (unsigned)iw < 64u)
        v = x[(((b * CIN + c) << 6) + ih) * 64 + iw];
    __nv_bfloat16 hi = __float2bfloat16(v);
    __nv_bfloat16 lo = __float2bfloat16(v - __bfloat162float(hi));
    size_t idx = (size_t)m * KDIM + k;
    g_colh[idx] = hi;
    g_coll[idx] = lo;
}

// ---------------- kernel 2: conv weight split + bias merge ----------------
__global__ __launch_bounds__(576) void wprep_k(const float* __restrict__ w_off,
                                               const float* __restrict__ b_off,
                                               const float* __restrict__ w_mod,
                                               const float* __restrict__ b_mod) {
    const int n = blockIdx.x;           // 0..1727
    const int k = threadIdx.x;          // 0..575
    float v = (n < NOFF) ? w_off[(size_t)n * KDIM + k]
                         : w_mod[(size_t)(n - NOFF) * KDIM + k];
    __nv_bfloat16 hi = __float2bfloat16(v);
    __nv_bfloat16 lo = __float2bfloat16(v - __bfloat162float(hi));
    size_t idx = (size_t)n * KDIM + k;
    g_wh[idx] = hi;
    g_wl[idx] = lo;
    if (k == 0)
        g_bias[n] = (n < NOFF) ? b_off[n] : b_mod[n - NOFF];
}

// ---------------- kernel 2b: w_conv split [o][j] ----------------
__global__ __launch_bounds__(576) void wcprep_k(const float* __restrict__ w_conv) {
    int idx = blockIdx.x * 576 + threadIdx.x;     // 128 blocks x 576
    float v = w_conv[idx];
    __nv_bfloat16 hi = __float2bfloat16(v);
    __nv_bfloat16 lo = __float2bfloat16(v - __bfloat162float(hi));
    g_wch[idx] = hi;
    g_wcl[idx] = lo;
}

// ---------------- kernel 3: mma.sync bf16x3 GEMM for offset+mask conv ----------------
#define BM 128
#define BN 96
#define BK 64
#define NSTAGE 3
#define A_STAGE (BM * BK * 2)            // 16384 B
#define B_STAGE (BN * BK * 2)            // 12288 B
#define STAGE_B (A_STAGE + B_STAGE)      // 28672 B
#define GEMM_SMEM (NSTAGE * STAGE_B)     // 86016 B
#define KCH 9                            // 576/64
#define VCHUNKS (3 * KCH)                // 27

__device__ __forceinline__ int swz(int r, int c) { return c ^ (r & 7); }

__global__ void __launch_bounds__(256, 2) gemm_mma_k() {
    extern __shared__ char sm[];
    const int tid = threadIdx.x;
    const int wid = tid >> 5;
    const int lane = tid & 31;
    const int warp_m = wid & 3;
    const int warp_n = wid >> 2;
    const int m0 = blockIdx.x * BM;
    const int n0 = blockIdx.y * BN;
    const uint32_t smem_base = smem_u32(sm);

    float acc[2][6][4];
#pragma unroll
    for (int i = 0; i < 2; i++)
#pragma unroll
        for (int j = 0; j < 6; j++)
#pragma unroll
            for (int q = 0; q < 4; q++) acc[i][j][q] = 0.f;

    auto load_stage = [&](int s, int chunk) {
        const int seg = chunk / KCH;
        const int k0 = (chunk - seg * KCH) * BK;
        const __nv_bfloat16* Asrc = (seg == 1) ? g_coll : g_colh;
        const __nv_bfloat16* Bsrc = (seg == 2) ? g_wl : g_wh;
        const uint32_t ab = smem_base + s * STAGE_B;
        const uint32_t bb = ab + A_STAGE;
#pragma unroll
        for (int i = 0; i < 4; i++) {
            int e = tid + i * 256;
            int r = e >> 3, c = e & 7;
            cp_async16(ab + r * 128 + swz(r, c) * 16,
                       Asrc + (size_t)(m0 + r) * KDIM + k0 + c * 8);
        }
#pragma unroll
        for (int i = 0; i < 3; i++) {
            int e = tid + i * 256;
            int r = e >> 3, c = e & 7;
            cp_async16(bb + r * 128 + swz(r, c) * 16,
                       Bsrc + (size_t)(n0 + r) * KDIM + k0 + c * 8);
        }
        asm volatile("cp.async.commit_group;");
    };

    load_stage(0, 0);
    load_stage(1, 1);

    for (int q = 0; q < VCHUNKS; q++) {
        asm volatile("cp.async.wait_group 1;");
        __syncthreads();
        if (q + 2 < VCHUNKS) load_stage((q + 2) % NSTAGE, q + 2);

        const uint32_t ab = smem_base + (q % NSTAGE) * STAGE_B;
        const uint32_t bb = ab + A_STAGE;
#pragma unroll
        for (int ks = 0; ks < 4; ks++) {
            uint32_t a[2][4];
#pragma unroll
            for (int mf = 0; mf < 2; mf++) {
                int r = warp_m * 32 + mf * 16 + (lane & 15);
                int c = ks * 2 + (lane >> 4);
                ldsm_x4(a[mf][0], a[mf][1], a[mf][2], a[mf][3],
                        ab + r * 128 + swz(r, c) * 16);
            }
#pragma unroll
            for (int nfp = 0; nfp < 3; nfp++) {
                int r = warp_n * 48 + nfp * 16 + (lane & 7) + ((lane >> 4) & 1) * 8;
                int c = ks * 2 + ((lane >> 3) & 1);
                uint32_t b[4];
                ldsm_x4(b[0], b[1], b[2], b[3], bb + r * 128 + swz(r, c) * 16);
                mma16816(acc[0][2 * nfp],     a[0], b);
                mma16816(acc[0][2 * nfp + 1], a[0], b + 2);
                mma16816(acc[1][2 * nfp],     a[1], b);
                mma16816(acc[1][2 * nfp + 1], a[1], b + 2);
            }
        }
    }
    __syncthreads();

    // epilogue: transpose via SMEM, coalesced [n][m] stores
    float* ws = (float*)sm + wid * (48 * 33);
#pragma unroll
    for (int mf = 0; mf < 2; mf++)
#pragma unroll
        for (int nf = 0; nf < 6; nf++)
#pragma unroll
            for (int j = 0; j < 4; j++) {
                int nl = (nf >> 1) * 16 + (nf & 1) * 8 + (lane & 3) * 2 + (j & 1);
                int ml = mf * 16 + ((j >> 1) & 1) * 8 + (lane >> 2);
                ws[nl * 33 + ml] = acc[mf][nf][j];
            }
    __syncwarp();
    {
        const int m = m0 + warp_m * 32 + lane;
#pragma unroll 4
        for (int row = 0; row < 48; row++) {
            int n = n0 + warp_n * 48 + row;
            float v = ws[row * 33 + lane] + g_bias[n];
            if (n < NOFF) {
                v = fminf(MAXOFF, fmaxf(-MAXOFF, v));
                g_off[(size_t)n * MTOT + m] = v;
            } else {
                g_mask[(size_t)(n - NOFF) * MTOT + m] = v;
            }
        }
    }
}

// ---------------- kernel 4: streaming deformable sampler ----------------
// Writes samp[j][m] = bilinear(x; off) * mask as bf16 hi/lo into g_colh/g_coll.
// grid (MTOT/128, 4), block 128; block covers 128 consecutive m, 16 channels.
__global__ __launch_bounds__(128) void sample_k(const float* __restrict__ x) {
    const int m = blockIdx.x * 128 + threadIdx.x;
    const int w = m & 63, h = (m >> 6) & 63, b = m >> 12;
    const float* xb = x + ((size_t)b * CIN << 12);
    const int c0 = blockIdx.y * 16;

    for (int cc = 0; cc < 16; cc++) {
        const int c = c0 + cc;
        const float* xp = xb + ((size_t)c << 12);
        const float* offp = g_off + (size_t)c * 18 * MTOT + m;
        const float* mp = g_mask + (size_t)c * KKK * MTOT + m;
#pragma unroll
        for (int kk = 0; kk < KKK; kk++) {
            const int ki = kk / 3, kj = kk - (kk / 3) * 3;
            float dy = offp[(size_t)(2 * kk) * MTOT];
            float dx = offp[(size_t)(2 * kk + 1) * MTOT];
            float mv = mp[(size_t)kk * MTOT];

            float py = dy + (float)(h + ki - 1);
            float px = dx + (float)(w + kj - 1);
            float v = 0.f;
            if (py > -1.f && py < 64.f && px > -1.f && px < 64.f) {
                float y0f = floorf(py), x0f = floorf(px);
                float wy = py - y0f, wx = px - x0f;
                int y0 = (int)y0f, x0 = (int)x0f;
                float v00 = 0.f, v01 = 0.f, v10 = 0.f, v11 = 0.f;
                bool yi0 = (unsigned)y0 < 64u;
                bool yi1 = (unsigned)(y0 + 1) < 64u;
                bool xi0 = (unsigned)x0 < 64u;
                bool xi1 = (unsigned)(x0 + 1) < 64u;
                if (yi0 && xi0) v00 = xp[(y0 << 6) + x0];
                if (yi0 && xi1) v01 = xp[(y0 << 6) + x0 + 1];
                if (yi1 && xi0) v10 = xp[((y0 + 1) << 6) + x0];
                if (yi1 && xi1) v11 = xp[((y0 + 1) << 6) + x0 + 1];
                v = (1.f - wy) * ((1.f - wx) * v00 + wx * v01) +
                    wy * ((1.f - wx) * v10 + wx * v11);
            }
            float s = v * mv;
            __nv_bfloat16 hi = __float2bfloat16(s);
            __nv_bfloat16 lo = __float2bfloat16(s - __bfloat162float(hi));
            size_t di = (size_t)(c * KKK + kk) * MTOT + m;
            g_colh[di] = hi;
            g_coll[di] = lo;
        }
    }
}

// ---------------- kernel 5: output GEMM  out[o][m] = sum_j w[o][j]*samp[j][m] ----------------
// A = g_wch/g_wcl [o][j] row-major (normal ldmatrix); B = samp [j][m] (ldmatrix.trans).
#define OBM 128
#define OBN 128
#define OBK 64
#define OA_STAGE (OBM * OBK * 2)          // 16384 B
#define OB_STAGE (OBK * OBN * 2)          // 16384 B
#define OSTAGE_B (OA_STAGE + OB_STAGE)    // 32768 B
#define OGEMM_SMEM (NSTAGE * OSTAGE_B)    // 98304 B

__global__ void __launch_bounds__(256, 2) out_gemm_k(float* __restrict__ out) {
    extern __shared__ char sm[];
    const int tid = threadIdx.x;
    const int wid = tid >> 5;
    const int lane = tid & 31;
    const int warp_o = wid & 1;       // 2 warps x 64 o
    const int warp_n = wid >> 1;      // 4 warps x 32 m
    const int mm0 = blockIdx.x * OBN;
    const uint32_t smem_base = smem_u32(sm);

    float acc[4][4][4];
#pragma unroll
    for (int i = 0; i < 4; i++)
#pragma unroll
        for (int j = 0; j < 4; j++)
#pragma unroll
            for (int q = 0; q < 4; q++) acc[i][j][q] = 0.f;

    auto load_stage = [&](int s, int chunk) {
        const int seg = chunk / KCH;
        const int k0 = (chunk - seg * KCH) * OBK;
        const __nv_bfloat16* Asrc = (seg == 1) ? g_wcl : g_wch;
        const __nv_bfloat16* Bsrc = (seg == 2) ? g_coll : g_colh;
        const uint32_t ab = smem_base + s * OSTAGE_B;
        const uint32_t bb = ab + OA_STAGE;
#pragma unroll
        for (int i = 0; i < 4; i++) {           // A: 128 rows x 8 chunks
            int e = tid + i * 256;
            int r = e >> 3, c = e & 7;
            cp_async16(ab + r * 128 + swz(r, c) * 16,
                       Asrc + (size_t)r * KDIM + k0 + c * 8);
        }
#pragma unroll
        for (int i = 0; i < 4; i++) {           // B: 64 rows x 16 chunks (256B pitch)
            int e = tid + i * 256;
            int r = e >> 4, c = e & 15;
            cp_async16(bb + r * 256 + (c ^ (r & 15)) * 16,
                       Bsrc + (size_t)(k0 + r) * MTOT + mm0 + c * 8);
        }
        asm volatile("cp.async.commit_group;");
    };

    load_stage(0, 0);
    load_stage(1, 1);

    for (int q = 0; q < VCHUNKS; q++) {
        asm volatile("cp.async.wait_group 1;");
        __syncthreads();
        if (q + 2 < VCHUNKS) load_stage((q + 2) % NSTAGE, q + 2);

        const uint32_t ab = smem_base + (q % NSTAGE) * OSTAGE_B;
        const uint32_t bb = ab + OA_STAGE;
#pragma unroll
        for (int ks = 0; ks < 4; ks++) {
            uint32_t a[4][4];
#pragma unroll
            for (int mf = 0; mf < 4; mf++) {
                int r = warp_o * 64 + mf * 16 + (lane & 15);
                int c = ks * 2 + (lane >> 4);
                ldsm_x4(a[mf][0], a[mf][1], a[mf][2], a[mf][3],
                        ab + r * 128 + swz(r, c) * 16);
            }
#pragma unroll
            for (int np = 0; np < 2; np++) {
                int j = ks * 16 + (lane & 15);
                int cn = warp_n * 4 + np * 2 + (lane >> 4);
                uint32_t b[4];
                ldsm_x4t(b[0], b[1], b[2], b[3],
                         bb + j * 256 + (cn ^ (j & 15)) * 16);
#pragma unroll
                for (int mf = 0; mf < 4; mf++) {
                    mma16816(acc[mf][np * 2],     a[mf], b);
                    mma16816(acc[mf][np * 2 + 1], a[mf], b + 2);
                }
            }
        }
    }

    // epilogue: direct stores, out[b][o][h][w], m contiguous within a row pair
    const int bidx = mm0 >> 12;
    const int rem0 = mm0 & 4095;
#pragma unroll
    for (int mf = 0; mf < 4; mf++) {
#pragma unroll
        for (int nf = 0; nf < 4; nf++) {
            int o = warp_o * 64 + mf * 16 + (lane >> 2);
            int mc = rem0 + warp_n * 32 + nf * 8 + (lane & 3) * 2;
            float* p0 = out + ((size_t)(bidx * OO + o) << 12) + mc;
            p0[0] = acc[mf][nf][0];
            p0[1] = acc[mf][nf][1];
            float* p1 = p0 + (8 << 12);
            p1[0] = acc[mf][nf][2];
            p1[1] = acc[mf][nf][3];
        }
    }
}

// ---------------- launch ----------------
extern "C" void kernel_launch(void* const* d_in, const int* in_sizes, int n_in,
                              void* d_out, int out_size) {
    const float* x      = (const float*)d_in[0];
    const float* w_off  = (const float*)d_in[1];
    const float* b_off  = (const float*)d_in[2];
    const float* w_mod  = (const float*)d_in[3];
    const float* b_mod  = (const float*)d_in[4];
    const float* w_conv = (const float*)d_in[5];
    float* out = (float*)d_out;

    static int smem_set = 0;
    if (!smem_set) {
        cudaFuncSetAttribute(gemm_mma_k, cudaFuncAttributeMaxDynamicSharedMemorySize, GEMM_SMEM);
        cudaFuncSetAttribute(out_gemm_k, cudaFuncAttributeMaxDynamicSharedMemorySize, OGEMM_SMEM);
        smem_set = 1;
    }

    im2col_bf16_k<<<MTOT, 576>>>(x);
    wprep_k<<<NTOT, 576>>>(w_off, b_off, w_mod, b_mod);
    wcprep_k<<<OO, 576>>>(w_conv);
    gemm_mma_k<<<dim3(MTOT / BM, NTOT / BN), 256, GEMM_SMEM>>>();
    sample_k<<<dim3(MTOT / 128, 4), 128>>>(x);
    out_gemm_k<<<MTOT / OBN, 256, OGEMM_SMEM>>>(out);
}

// round 9
// speedup vs baseline: 3.3597x; 1.0185x over previous
#include <cuda_runtime.h>
#include <cuda_bf16.h>
#include <cstdint>
#include <math.h>

// ---------------- problem constants ----------------
#define NB    8
#define CIN   64
#define OO    128
#define KKK   9
#define KDIM  576          // CIN * 9
#define NOFF  1152         // 2 * CIN * 9
#define NTOT  1728         // offset + mask channels
#define MTOT  32768        // NB * H * W
#define MAXOFF 16.0f

// ---------------- scratch (device globals, allocation-free) ----------------
// g_colh/g_coll double as: im2col [m][k] for gemm_mma_k, then sample matrix
// [j][m] for out_gemm_k (gemm_mma_k completes before sample_k overwrites).
__device__ __align__(16) __nv_bfloat16 g_colh[(size_t)MTOT * KDIM];
__device__ __align__(16) __nv_bfloat16 g_coll[(size_t)MTOT * KDIM];
__device__ __align__(16) __nv_bfloat16 g_wh  [(size_t)NTOT * KDIM];  // conv weights hi [n][k]
__device__ __align__(16) __nv_bfloat16 g_wl  [(size_t)NTOT * KDIM];  // conv weights lo [n][k]
__device__ __align__(16) __nv_bfloat16 g_wch [OO * KDIM];            // w_conv hi [o][j]
__device__ __align__(16) __nv_bfloat16 g_wcl [OO * KDIM];            // w_conv lo [o][j]
__device__ float g_bias[NTOT];
__device__ float g_off [(size_t)NOFF * MTOT];            // offsets [n][m]
__device__ float g_mask[(size_t)(NTOT - NOFF) * MTOT];   // mask    [n][m]

// ---------------- PTX helpers (baseline sm_80+ features only) ----------------
__device__ __forceinline__ uint32_t smem_u32(const void* p) {
    uint32_t a;
    asm("{ .reg .u64 t; cvta.to.shared.u64 t, %1; cvt.u32.u64 %0, t; }" : "=r"(a) : "l"(p));
    return a;
}
__device__ __forceinline__ void cp_async16(uint32_t dst, const void* src) {
    asm volatile("cp.async.cg.shared.global [%0], [%1], 16;" :: "r"(dst), "l"(src));
}
__device__ __forceinline__ void ldsm_x4(uint32_t& r0, uint32_t& r1, uint32_t& r2, uint32_t& r3,
                                        uint32_t addr) {
    asm volatile("ldmatrix.sync.aligned.m8n8.x4.shared.b16 {%0,%1,%2,%3}, [%4];"
                 : "=r"(r0), "=r"(r1), "=r"(r2), "=r"(r3) : "r"(addr));
}
__device__ __forceinline__ void ldsm_x4t(uint32_t& r0, uint32_t& r1, uint32_t& r2, uint32_t& r3,
                                         uint32_t addr) {
    asm volatile("ldmatrix.sync.aligned.m8n8.x4.trans.shared.b16 {%0,%1,%2,%3}, [%4];"
                 : "=r"(r0), "=r"(r1), "=r"(r2), "=r"(r3) : "r"(addr));
}
__device__ __forceinline__ void mma16816(float* d, const uint32_t* a, const uint32_t* b) {
    asm volatile(
        "mma.sync.aligned.m16n8k16.row.col.f32.bf16.bf16.f32 "
        "{%0,%1,%2,%3}, {%4,%5,%6,%7}, {%8,%9}, {%0,%1,%2,%3};"
        : "+f"(d[0]), "+f"(d[1]), "+f"(d[2]), "+f"(d[3])
        : "r"(a[0]), "r"(a[1]), "r"(a[2]), "r"(a[3]), "r"(b[0]), "r"(b[1]));
}

// ---------------- kernel 1: im2col -> bf16 hi/lo in [m][k] layout ----------------
__global__ __launch_bounds__(576) void im2col_bf16_k(const float* __restrict__ x) {
    const int m = blockIdx.x;
    const int k = threadIdx.x;          // 0..575
    const int w = m & 63, h = (m >> 6) & 63, b = m >> 12;
    const int c = k / KKK, kk = k - c * KKK;
    const int ki = kk / 3, kj = kk - ki * 3;
    const int ih = h + ki - 1, iw = w + kj - 1;
    float v = 0.f;
    if ((unsigned)ih < 64u && (unsigned)iw < 64u)
        v = x[(((b * CIN + c) << 6) + ih) * 64 + iw];
    __nv_bfloat16 hi = __float2bfloat16(v);
    __nv_bfloat16 lo = __float2bfloat16(v - __bfloat162float(hi));
    size_t idx = (size_t)m * KDIM + k;
    g_colh[idx] = hi;
    g_coll[idx] = lo;
}

// ---------------- kernel 2: conv weight split + bias merge ----------------
__global__ __launch_bounds__(576) void wprep_k(const float* __restrict__ w_off,
                                               const float* __restrict__ b_off,
                                               const float* __restrict__ w_mod,
                                               const float* __restrict__ b_mod) {
    const int n = blockIdx.x;           // 0..1727
    const int k = threadIdx.x;          // 0..575
    float v = (n < NOFF) ? w_off[(size_t)n * KDIM + k]
                         : w_mod[(size_t)(n - NOFF) * KDIM + k];
    __nv_bfloat16 hi = __float2bfloat16(v);
    __nv_bfloat16 lo = __float2bfloat16(v - __bfloat162float(hi));
    size_t idx = (size_t)n * KDIM + k;
    g_wh[idx] = hi;
    g_wl[idx] = lo;
    if (k == 0)
        g_bias[n] = (n < NOFF) ? b_off[n] : b_mod[n - NOFF];
}

// ---------------- kernel 2b: w_conv split [o][j] ----------------
__global__ __launch_bounds__(576) void wcprep_k(const float* __restrict__ w_conv) {
    int idx = blockIdx.x * 576 + threadIdx.x;     // 128 blocks x 576
    float v = w_conv[idx];
    __nv_bfloat16 hi = __float2bfloat16(v);
    __nv_bfloat16 lo = __float2bfloat16(v - __bfloat162float(hi));
    g_wch[idx] = hi;
    g_wcl[idx] = lo;
}

// ---------------- kernel 3: fused bf16x3 GEMM for offset+mask conv ----------------
// D[m][n] = sum_k col[m][k] * w[n][k].  Per 32-wide k-chunk the stage holds
// hi|lo interleaved per 128B row: chunks 0-3 = hi k[0:32], chunks 4-7 = lo.
// One load feeds all three products AhBh + AlBh + AhBl.
#define BM 128
#define BN 96
#define BK 32
#define NSTAGE 3
#define A_STAGE (BM * 128)               // 16384 B (hi|lo per row)
#define B_STAGE (BN * 128)               // 12288 B
#define STAGE_B (A_STAGE + B_STAGE)      // 28672 B
#define GEMM_SMEM (NSTAGE * STAGE_B)     // 86016 B
#define VCHUNKS 18                       // 576/32

__device__ __forceinline__ int swz(int r, int c) { return c ^ (r & 7); }

__global__ void __launch_bounds__(256, 2) gemm_mma_k() {
    extern __shared__ char sm[];
    const int tid = threadIdx.x;
    const int wid = tid >> 5;
    const int lane = tid & 31;
    const int warp_m = wid & 3;
    const int warp_n = wid >> 2;
    const int m0 = blockIdx.x * BM;
    const int n0 = blockIdx.y * BN;
    const uint32_t smem_base = smem_u32(sm);

    float acc[2][6][4];
#pragma unroll
    for (int i = 0; i < 2; i++)
#pragma unroll
        for (int j = 0; j < 6; j++)
#pragma unroll
            for (int q = 0; q < 4; q++) acc[i][j][q] = 0.f;

    auto load_stage = [&](int s, int chunk) {
        const int k0 = chunk * BK;
        const uint32_t ab = smem_base + s * STAGE_B;
        const uint32_t bb = ab + A_STAGE;
#pragma unroll
        for (int i = 0; i < 4; i++) {          // A: 1024 chunks (hi: c<4, lo: c>=4)
            int e = tid + i * 256;
            int r = e >> 3, c = e & 7;
            const __nv_bfloat16* src = (c & 4) ? g_coll : g_colh;
            cp_async16(ab + r * 128 + swz(r, c) * 16,
                       src + (size_t)(m0 + r) * KDIM + k0 + (c & 3) * 8);
        }
#pragma unroll
        for (int i = 0; i < 3; i++) {          // B: 768 chunks
            int e = tid + i * 256;
            int r = e >> 3, c = e & 7;
            const __nv_bfloat16* src = (c & 4) ? g_wl : g_wh;
            cp_async16(bb + r * 128 + swz(r, c) * 16,
                       src + (size_t)(n0 + r) * KDIM + k0 + (c & 3) * 8);
        }
        asm volatile("cp.async.commit_group;");
    };

    load_stage(0, 0);
    load_stage(1, 1);

    for (int q = 0; q < VCHUNKS; q++) {
        asm volatile("cp.async.wait_group 1;");
        __syncthreads();
        if (q + 2 < VCHUNKS) load_stage((q + 2) % NSTAGE, q + 2);

        const uint32_t ab = smem_base + (q % NSTAGE) * STAGE_B;
        const uint32_t bb = ab + A_STAGE;
#pragma unroll
        for (int ks = 0; ks < 2; ks++) {       // 2 x k16 within BK=32
            uint32_t ah[2][4], al[2][4];
#pragma unroll
            for (int mf = 0; mf < 2; mf++) {
                int r = warp_m * 32 + mf * 16 + (lane & 15);
                int ch = ks * 2 + (lane >> 4);           // 0..3 (hi)
                ldsm_x4(ah[mf][0], ah[mf][1], ah[mf][2], ah[mf][3],
                        ab + r * 128 + swz(r, ch) * 16);
                ldsm_x4(al[mf][0], al[mf][1], al[mf][2], al[mf][3],
                        ab + r * 128 + swz(r, ch + 4) * 16);
            }
#pragma unroll
            for (int nfp = 0; nfp < 3; nfp++) {
                int r = warp_n * 48 + nfp * 16 + (lane & 7) + ((lane >> 4) & 1) * 8;
                int ch = ks * 2 + ((lane >> 3) & 1);
                uint32_t bh[4], bl[4];
                ldsm_x4(bh[0], bh[1], bh[2], bh[3], bb + r * 128 + swz(r, ch) * 16);
                ldsm_x4(bl[0], bl[1], bl[2], bl[3], bb + r * 128 + swz(r, ch + 4) * 16);
                // Ah*Bh
                mma16816(acc[0][2 * nfp],     ah[0], bh);
                mma16816(acc[0][2 * nfp + 1], ah[0], bh + 2);
                mma16816(acc[1][2 * nfp],     ah[1], bh);
                mma16816(acc[1][2 * nfp + 1], ah[1], bh + 2);
                // Al*Bh
                mma16816(acc[0][2 * nfp],     al[0], bh);
                mma16816(acc[0][2 * nfp + 1], al[0], bh + 2);
                mma16816(acc[1][2 * nfp],     al[1], bh);
                mma16816(acc[1][2 * nfp + 1], al[1], bh + 2);
                // Ah*Bl
                mma16816(acc[0][2 * nfp],     ah[0], bl);
                mma16816(acc[0][2 * nfp + 1], ah[0], bl + 2);
                mma16816(acc[1][2 * nfp],     ah[1], bl);
                mma16816(acc[1][2 * nfp + 1], ah[1], bl + 2);
            }
        }
    }
    __syncthreads();

    // epilogue: transpose via SMEM, coalesced [n][m] stores
    float* ws = (float*)sm + wid * (48 * 33);
#pragma unroll
    for (int mf = 0; mf < 2; mf++)
#pragma unroll
        for (int nf = 0; nf < 6; nf++)
#pragma unroll
            for (int j = 0; j < 4; j++) {
                int nl = (nf >> 1) * 16 + (nf & 1) * 8 + (lane & 3) * 2 + (j & 1);
                int ml = mf * 16 + ((j >> 1) & 1) * 8 + (lane >> 2);
                ws[nl * 33 + ml] = acc[mf][nf][j];
            }
    __syncwarp();
    {
        const int m = m0 + warp_m * 32 + lane;
#pragma unroll 4
        for (int row = 0; row < 48; row++) {
            int n = n0 + warp_n * 48 + row;
            float v = ws[row * 33 + lane] + g_bias[n];
            if (n < NOFF) {
                v = fminf(MAXOFF, fmaxf(-MAXOFF, v));
                g_off[(size_t)n * MTOT + m] = v;
            } else {
                g_mask[(size_t)(n - NOFF) * MTOT + m] = v;
            }
        }
    }
}

// ---------------- kernel 4: streaming deformable sampler ----------------
__global__ __launch_bounds__(128) void sample_k(const float* __restrict__ x) {
    const int m = blockIdx.x * 128 + threadIdx.x;
    const int w = m & 63, h = (m >> 6) & 63, b = m >> 12;
    const float* xb = x + ((size_t)b * CIN << 12);
    const int c0 = blockIdx.y * 16;

    for (int cc = 0; cc < 16; cc++) {
        const int c = c0 + cc;
        const float* xp = xb + ((size_t)c << 12);
        const float* offp = g_off + (size_t)c * 18 * MTOT + m;
        const float* mp = g_mask + (size_t)c * KKK * MTOT + m;
#pragma unroll
        for (int kk = 0; kk < KKK; kk++) {
            const int ki = kk / 3, kj = kk - (kk / 3) * 3;
            float dy = offp[(size_t)(2 * kk) * MTOT];
            float dx = offp[(size_t)(2 * kk + 1) * MTOT];
            float mv = mp[(size_t)kk * MTOT];

            float py = dy + (float)(h + ki - 1);
            float px = dx + (float)(w + kj - 1);
            float v = 0.f;
            if (py > -1.f && py < 64.f && px > -1.f && px < 64.f) {
                float y0f = floorf(py), x0f = floorf(px);
                float wy = py - y0f, wx = px - x0f;
                int y0 = (int)y0f, x0 = (int)x0f;
                float v00 = 0.f, v01 = 0.f, v10 = 0.f, v11 = 0.f;
                bool yi0 = (unsigned)y0 < 64u;
                bool yi1 = (unsigned)(y0 + 1) < 64u;
                bool xi0 = (unsigned)x0 < 64u;
                bool xi1 = (unsigned)(x0 + 1) < 64u;
                if (yi0 && xi0) v00 = xp[(y0 << 6) + x0];
                if (yi0 && xi1) v01 = xp[(y0 << 6) + x0 + 1];
                if (yi1 && xi0) v10 = xp[((y0 + 1) << 6) + x0];
                if (yi1 && xi1) v11 = xp[((y0 + 1) << 6) + x0 + 1];
                v = (1.f - wy) * ((1.f - wx) * v00 + wx * v01) +
                    wy * ((1.f - wx) * v10 + wx * v11);
            }
            float s = v * mv;
            __nv_bfloat16 hi = __float2bfloat16(s);
            __nv_bfloat16 lo = __float2bfloat16(s - __bfloat162float(hi));
            size_t di = (size_t)(c * KKK + kk) * MTOT + m;
            g_colh[di] = hi;
            g_coll[di] = lo;
        }
    }
}

// ---------------- kernel 5: output GEMM  out[o][m] = sum_j w[o][j]*samp[j][m] ----------------
#define OBM 128
#define OBN 128
#define OBK 64
#define OA_STAGE (OBM * OBK * 2)          // 16384 B
#define OB_STAGE (OBK * OBN * 2)          // 16384 B
#define OSTAGE_B (OA_STAGE + OB_STAGE)    // 32768 B
#define OGEMM_SMEM (NSTAGE * OSTAGE_B)    // 98304 B
#define OKCH 9                            // 576/64
#define OVCHUNKS (3 * OKCH)               // 27

__global__ void __launch_bounds__(256, 2) out_gemm_k(float* __restrict__ out) {
    extern __shared__ char sm[];
    const int tid = threadIdx.x;
    const int wid = tid >> 5;
    const int lane = tid & 31;
    const int warp_o = wid & 1;       // 2 warps x 64 o
    const int warp_n = wid >> 1;      // 4 warps x 32 m
    const int mm0 = blockIdx.x * OBN;
    const uint32_t smem_base = smem_u32(sm);

    float acc[4][4][4];
#pragma unroll
    for (int i = 0; i < 4; i++)
#pragma unroll
        for (int j = 0; j < 4; j++)
#pragma unroll
            for (int q = 0; q < 4; q++) acc[i][j][q] = 0.f;

    auto load_stage = [&](int s, int chunk) {
        const int seg = chunk / OKCH;
        const int k0 = (chunk - seg * OKCH) * OBK;
        const __nv_bfloat16* Asrc = (seg == 1) ? g_wcl : g_wch;
        const __nv_bfloat16* Bsrc = (seg == 2) ? g_coll : g_colh;
        const uint32_t ab = smem_base + s * OSTAGE_B;
        const uint32_t bb = ab + OA_STAGE;
#pragma unroll
        for (int i = 0; i < 4; i++) {
            int e = tid + i * 256;
            int r = e >> 3, c = e & 7;
            cp_async16(ab + r * 128 + swz(r, c) * 16,
                       Asrc + (size_t)r * KDIM + k0 + c * 8);
        }
#pragma unroll
        for (int i = 0; i < 4; i++) {
            int e = tid + i * 256;
            int r = e >> 4, c = e & 15;
            cp_async16(bb + r * 256 + (c ^ (r & 15)) * 16,
                       Bsrc + (size_t)(k0 + r) * MTOT + mm0 + c * 8);
        }
        asm volatile("cp.async.commit_group;");
    };

    load_stage(0, 0);
    load_stage(1, 1);

    for (int q = 0; q < OVCHUNKS; q++) {
        asm volatile("cp.async.wait_group 1;");
        __syncthreads();
        if (q + 2 < OVCHUNKS) load_stage((q + 2) % NSTAGE, q + 2);

        const uint32_t ab = smem_base + (q % NSTAGE) * OSTAGE_B;
        const uint32_t bb = ab + OA_STAGE;
#pragma unroll
        for (int ks = 0; ks < 4; ks++) {
            uint32_t a[4][4];
#pragma unroll
            for (int mf = 0; mf < 4; mf++) {
                int r = warp_o * 64 + mf * 16 + (lane & 15);
                int c = ks * 2 + (lane >> 4);
                ldsm_x4(a[mf][0], a[mf][1], a[mf][2], a[mf][3],
                        ab + r * 128 + swz(r, c) * 16);
            }
#pragma unroll
            for (int np = 0; np < 2; np++) {
                int j = ks * 16 + (lane & 15);
                int cn = warp_n * 4 + np * 2 + (lane >> 4);
                uint32_t b[4];
                ldsm_x4t(b[0], b[1], b[2], b[3],
                         bb + j * 256 + (cn ^ (j & 15)) * 16);
#pragma unroll
                for (int mf = 0; mf < 4; mf++) {
                    mma16816(acc[mf][np * 2],     a[mf], b);
                    mma16816(acc[mf][np * 2 + 1], a[mf], b + 2);
                }
            }
        }
    }

    // epilogue: direct stores, out[b][o][h][w]
    const int bidx = mm0 >> 12;
    const int rem0 = mm0 & 4095;
#pragma unroll
    for (int mf = 0; mf < 4; mf++) {
#pragma unroll
        for (int nf = 0; nf < 4; nf++) {
            int o = warp_o * 64 + mf * 16 + (lane >> 2);
            int mc = rem0 + warp_n * 32 + nf * 8 + (lane & 3) * 2;
            float* p0 = out + ((size_t)(bidx * OO + o) << 12) + mc;
            p0[0] = acc[mf][nf][0];
            p0[1] = acc[mf][nf][1];
            float* p1 = p0 + (8 << 12);
            p1[0] = acc[mf][nf][2];
            p1[1] = acc[mf][nf][3];
        }
    }
}

// ---------------- launch ----------------
extern "C" void kernel_launch(void* const* d_in, const int* in_sizes, int n_in,
                              void* d_out, int out_size) {
    const float* x      = (const float*)d_in[0];
    const float* w_off  = (const float*)d_in[1];
    const float* b_off  = (const float*)d_in[2];
    const float* w_mod  = (const float*)d_in[3];
    const float* b_mod  = (const float*)d_in[4];
    const float* w_conv = (const float*)d_in[5];
    float* out = (float*)d_out;

    static int smem_set = 0;
    if (!smem_set) {
        cudaFuncSetAttribute(gemm_mma_k, cudaFuncAttributeMaxDynamicSharedMemorySize, GEMM_SMEM);
        cudaFuncSetAttribute(out_gemm_k, cudaFuncAttributeMaxDynamicSharedMemorySize, OGEMM_SMEM);
        smem_set = 1;
    }

    im2col_bf16_k<<<MTOT, 576>>>(x);
    wprep_k<<<NTOT, 576>>>(w_off, b_off, w_mod, b_mod);
    wcprep_k<<<OO, 576>>>(w_conv);
    gemm_mma_k<<<dim3(MTOT / BM, NTOT / BN), 256, GEMM_SMEM>>>();
    sample_k<<<dim3(MTOT / 128, 4), 128>>>(x);
    out_gemm_k<<<MTOT / OBN, 256, OGEMM_SMEM>>>(out);
}